// round 1
// baseline (speedup 1.0000x reference)
#include <cuda_runtime.h>
#include <math.h>

#define NP 100000
#define NA 50000
#define EE 250000
#define HIDD 128
#define INV_SQRT_D 0.17677669529663687f

// ---------------- scratch (static device globals; no allocation) ----------------
__device__ float g_x_p[NP*HIDD];
__device__ float g_x_a[NA*HIDD];
__device__ float g_q_p[NP*HIDD];
__device__ float g_q_a[NA*HIDD];
__device__ float g_kr[NP*HIDD];
__device__ float g_vr[NP*HIDD];
__device__ float g_msg0[NP*HIDD];   // writes  (author->paper) unnormalized messages
__device__ float g_msg2[NP*HIDD];   // cites   (paper->paper)
__device__ float g_msg1[NA*HIDD];   // rev_writes (paper->author)
__device__ float g_den0[NP*4];
__device__ float g_den2[NP*4];
__device__ float g_den1[NA*4];
__device__ float g_act_p[NP*HIDD];
__device__ float g_act_a[NA*HIDD];
__device__ float g_wc[12*HIDD*HIDD];  // combined (k_w@a_rel / v_w@m_rel) per (l,e,{k,v})
__device__ float g_bc[12*HIDD];

__device__ __forceinline__ float gelu_f(float x) {
    return 0.5f * x * (1.0f + erff(x * 0.70710678118654752f));
}

// ---------------- precompute combined relation weights ----------------
// unit = (l*3+e)*2 + which;  which: 0 -> (k_w, a_rel), 1 -> (v_w, m_rel)
// Wc[r][h*32+c] = sum_d W[r][h*32+d] * R[h][d][c];  bc likewise from bias.
__global__ void make_wc(const float* __restrict__ kw, const float* __restrict__ kb,
                        const float* __restrict__ vw, const float* __restrict__ vb,
                        const float* __restrict__ arel, const float* __restrict__ mrel)
{
    int unit = blockIdx.x >> 3;      // 0..11
    int part = blockIdx.x & 7;       // 0..7 (rows part*16 .. +15)
    int which = unit & 1;
    int le = unit >> 1;              // l*3+e
    int e = le % 3;
    int l = le / 3;
    int s = (e == 0) ? 1 : 0;        // source node type

    const float* W = (which ? vw : kw) + (size_t)(l*2 + s) * (HIDD*HIDD);
    const float* B = (which ? vb : kb) + (size_t)(l*2 + s) * HIDD;
    const float* R = (which ? mrel : arel) + (size_t)le * 4096;  // [4][32][32]

    __shared__ float Rs[4096];
    for (int i = threadIdx.x; i < 4096; i += blockDim.x) Rs[i] = R[i];
    __syncthreads();

    float* outW = g_wc + (size_t)unit * (HIDD*HIDD);
    for (int idx = part*2048 + threadIdx.x; idx < (part+1)*2048; idx += blockDim.x) {
        int r = idx >> 7, col = idx & 127;
        int h = col >> 5, c = col & 31;
        float acc = 0.f;
        const float* wr = W + (size_t)r*HIDD + h*32;
        const float* rr = Rs + h*1024 + c;
        #pragma unroll
        for (int d = 0; d < 32; d++) acc = fmaf(wr[d], rr[d*32], acc);
        outW[idx] = acc;
    }
    if (part == 0) {
        for (int col = threadIdx.x; col < HIDD; col += blockDim.x) {
            int h = col >> 5, c = col & 31;
            float acc = 0.f;
            #pragma unroll
            for (int d = 0; d < 32; d++) acc = fmaf(B[h*32+d], Rs[h*1024 + d*32 + c], acc);
            g_bc[unit*HIDD + col] = acc;
        }
    }
}

// ---------------- generic [N,128]@[128,128]+bias GEMM ----------------
// mode 0: Y = X@W + b
// mode 1: Y = g*(X@W + b) + (1-g)*Xold   with g = sigmoid(*skipPtr)
__global__ __launch_bounds__(256, 2) void gemm128(
    const float* __restrict__ X, const float* __restrict__ W,
    const float* __restrict__ Bias, float* __restrict__ Y, int N,
    int mode, const float* __restrict__ Xold, const float* __restrict__ skipPtr)
{
    __shared__ float Xs[32][132];   // transposed: Xs[k][row]
    __shared__ float Ws[32][128];
    const int tid = threadIdx.x;
    const int row0 = blockIdx.x * 128;
    const int tx = tid & 15;        // 16 col groups * 8 cols
    const int ty = tid >> 4;        // 16 row groups * 8 rows

    float acc[8][8];
    #pragma unroll
    for (int i = 0; i < 8; i++)
        #pragma unroll
        for (int j = 0; j < 8; j++) acc[i][j] = 0.f;

    for (int kc = 0; kc < 128; kc += 32) {
        #pragma unroll
        for (int i = 0; i < 4; i++) {
            int li = tid + i*256;        // 0..1023 float4s of X tile
            int r  = li >> 3;            // row in tile (0..127)
            int c4 = (li & 7) << 2;      // k offset in chunk
            float4 v = make_float4(0.f, 0.f, 0.f, 0.f);
            if (row0 + r < N)
                v = *(const float4*)&X[(size_t)(row0 + r)*128 + kc + c4];
            Xs[c4+0][r] = v.x; Xs[c4+1][r] = v.y; Xs[c4+2][r] = v.z; Xs[c4+3][r] = v.w;
        }
        #pragma unroll
        for (int i = 0; i < 4; i++) {
            int li = tid + i*256;        // 0..1023 float4s of W chunk
            int r  = li >> 5;            // k row (0..31)
            int c4 = (li & 31) << 2;     // col
            *(float4*)&Ws[r][c4] = *(const float4*)&W[(size_t)(kc + r)*128 + c4];
        }
        __syncthreads();
        #pragma unroll
        for (int k = 0; k < 32; k++) {
            float a[8], b[8];
            *(float4*)&a[0] = *(const float4*)&Xs[k][ty*8];
            *(float4*)&a[4] = *(const float4*)&Xs[k][ty*8 + 4];
            *(float4*)&b[0] = *(const float4*)&Ws[k][tx*8];
            *(float4*)&b[4] = *(const float4*)&Ws[k][tx*8 + 4];
            #pragma unroll
            for (int i = 0; i < 8; i++)
                #pragma unroll
                for (int j = 0; j < 8; j++)
                    acc[i][j] = fmaf(a[i], b[j], acc[i][j]);
        }
        __syncthreads();
    }

    float g = 1.f, og = 0.f;
    if (mode == 1) { float sv = *skipPtr; g = 1.f / (1.f + expf(-sv)); og = 1.f - g; }

    #pragma unroll
    for (int i = 0; i < 8; i++) {
        int r = row0 + ty*8 + i;
        if (r < N) {
            #pragma unroll
            for (int j = 0; j < 8; j += 4) {
                int c = tx*8 + j;
                float4 o;
                o.x = acc[i][j+0] + Bias[c+0];
                o.y = acc[i][j+1] + Bias[c+1];
                o.z = acc[i][j+2] + Bias[c+2];
                o.w = acc[i][j+3] + Bias[c+3];
                if (mode == 1) {
                    float4 xo = *(const float4*)&Xold[(size_t)r*128 + c];
                    o.x = g*o.x + og*xo.x; o.y = g*o.y + og*xo.y;
                    o.z = g*o.z + og*xo.z; o.w = g*o.w + og*xo.w;
                }
                *(float4*)&Y[(size_t)r*128 + c] = o;
            }
        }
    }
}

// ---------------- author embedding gather ----------------
__global__ void gather_embed(const float* __restrict__ tab, const int* __restrict__ idx)
{
    int t = blockIdx.x * blockDim.x + threadIdx.x;
    if (t >= NA*32) return;
    int row = t >> 5, c = t & 31;
    ((float4*)g_x_a)[t] = ((const float4*)tab)[(size_t)idx[row]*32 + c];
}

// ---------------- fused edge pass ----------------
// one warp per edge: score per head, ex=exp(score*p_rel/sqrt(d)),
// den[dst,h] += ex (atomic), msg[dst,:] += ex * v_rel[src,:] (red.v4)
__global__ void edge_pass(const int* __restrict__ src, const int* __restrict__ dst,
                          const float* __restrict__ KR, const float* __restrict__ VR,
                          const float* __restrict__ Q, const float* __restrict__ prel,
                          float* __restrict__ den, float* __restrict__ msg, int E)
{
    int w = (blockIdx.x * blockDim.x + threadIdx.x) >> 5;
    int lane = threadIdx.x & 31;
    if (w >= E) return;
    int s = src[w];
    int d = dst[w];
    const float4 kr = *(const float4*)&KR[(size_t)s*128 + lane*4];
    const float4 q4 = *(const float4*)&Q [(size_t)d*128 + lane*4];
    const float4 vr = *(const float4*)&VR[(size_t)s*128 + lane*4];
    float p = kr.x*q4.x + kr.y*q4.y + kr.z*q4.z + kr.w*q4.w;
    p += __shfl_xor_sync(0xffffffffu, p, 4);
    p += __shfl_xor_sync(0xffffffffu, p, 2);
    p += __shfl_xor_sync(0xffffffffu, p, 1);
    int h = lane >> 3;
    float ex = expf(p * prel[h] * INV_SQRT_D);
    if ((lane & 7) == 0) atomicAdd(&den[(size_t)d*4 + h], ex);
    float* ptr = &msg[(size_t)d*128 + lane*4];
    asm volatile("red.global.add.v4.f32 [%0], {%1, %2, %3, %4};"
                 :: "l"(ptr), "f"(vr.x*ex), "f"(vr.y*ex), "f"(vr.z*ex), "f"(vr.w*ex)
                 : "memory");
}

// ---------------- combine (normalize + mean over edge types + gelu) ----------------
__global__ void combine_paper()
{
    int t = blockIdx.x * blockDim.x + threadIdx.x;
    if (t >= NP*32) return;
    int row = t >> 5, h = (t & 31) >> 3;
    float d0 = g_den0[row*4 + h] + 1e-16f;
    float d2 = g_den2[row*4 + h] + 1e-16f;
    float4 a = ((const float4*)g_msg0)[t];
    float4 b = ((const float4*)g_msg2)[t];
    float4 o;
    o.x = gelu_f(0.5f*(a.x/d0 + b.x/d2));
    o.y = gelu_f(0.5f*(a.y/d0 + b.y/d2));
    o.z = gelu_f(0.5f*(a.z/d0 + b.z/d2));
    o.w = gelu_f(0.5f*(a.w/d0 + b.w/d2));
    ((float4*)g_act_p)[t] = o;
}

__global__ void combine_author()
{
    int t = blockIdx.x * blockDim.x + threadIdx.x;
    if (t >= NA*32) return;
    int row = t >> 5, h = (t & 31) >> 3;
    float d1 = g_den1[row*4 + h] + 1e-16f;
    float4 a = ((const float4*)g_msg1)[t];
    float4 o;
    o.x = gelu_f(a.x/d1);
    o.y = gelu_f(a.y/d1);
    o.z = gelu_f(a.z/d1);
    o.w = gelu_f(a.w/d1);
    ((float4*)g_act_a)[t] = o;
}

// ---------------- driver ----------------
extern "C" void kernel_launch(void* const* d_in, const int* in_sizes, int n_in,
                              void* d_out, int out_size)
{
    const float* x_paper    = (const float*)d_in[0];
    const int*   author_idx = (const int*)  d_in[1];
    const float* embed      = (const float*)d_in[2];
    const float* lin_w      = (const float*)d_in[3];
    const float* lin_b      = (const float*)d_in[4];
    const float* k_w        = (const float*)d_in[5];
    const float* k_b        = (const float*)d_in[6];
    const float* q_w        = (const float*)d_in[7];
    const float* q_b        = (const float*)d_in[8];
    const float* v_w        = (const float*)d_in[9];
    const float* v_b        = (const float*)d_in[10];
    const float* a_rel      = (const float*)d_in[11];
    const float* m_rel      = (const float*)d_in[12];
    const float* p_rel      = (const float*)d_in[13];
    const float* skip       = (const float*)d_in[14];
    const float* a_w        = (const float*)d_in[15];
    const float* a_b        = (const float*)d_in[16];
    const int*   w_src      = (const int*)  d_in[17];
    const int*   w_dst      = (const int*)  d_in[18];
    const int*   r_src      = (const int*)  d_in[19];
    const int*   r_dst      = (const int*)  d_in[20];
    const int*   c_src      = (const int*)  d_in[21];
    const int*   c_dst      = (const int*)  d_in[22];
    float* out = (float*)d_out;

    float *xp, *xa, *qp, *qa, *kr, *vr, *m0, *m2, *m1, *dn0, *dn2, *dn1, *ap, *aa, *wc, *bc;
    cudaGetSymbolAddress((void**)&xp,  g_x_p);
    cudaGetSymbolAddress((void**)&xa,  g_x_a);
    cudaGetSymbolAddress((void**)&qp,  g_q_p);
    cudaGetSymbolAddress((void**)&qa,  g_q_a);
    cudaGetSymbolAddress((void**)&kr,  g_kr);
    cudaGetSymbolAddress((void**)&vr,  g_vr);
    cudaGetSymbolAddress((void**)&m0,  g_msg0);
    cudaGetSymbolAddress((void**)&m2,  g_msg2);
    cudaGetSymbolAddress((void**)&m1,  g_msg1);
    cudaGetSymbolAddress((void**)&dn0, g_den0);
    cudaGetSymbolAddress((void**)&dn2, g_den2);
    cudaGetSymbolAddress((void**)&dn1, g_den1);
    cudaGetSymbolAddress((void**)&ap,  g_act_p);
    cudaGetSymbolAddress((void**)&aa,  g_act_a);
    cudaGetSymbolAddress((void**)&wc,  g_wc);
    cudaGetSymbolAddress((void**)&bc,  g_bc);

    const int GP = (NP + 127) / 128;
    const int GA = (NA + 127) / 128;
    const int GE = (EE * 32 + 255) / 256;

    // combined relation weights for all (layer, edge, {k,v})
    make_wc<<<96, 256>>>(k_w, k_b, v_w, v_b, a_rel, m_rel);

    // input features
    gemm128<<<GP, 256>>>(x_paper, lin_w, lin_b, xp, NP, 0, nullptr, nullptr);
    gather_embed<<<(NA*32 + 255)/256, 256>>>(embed, author_idx);

    for (int l = 0; l < 2; l++) {
        cudaMemsetAsync(m0,  0, (size_t)NP*128*4, 0);
        cudaMemsetAsync(m2,  0, (size_t)NP*128*4, 0);
        cudaMemsetAsync(m1,  0, (size_t)NA*128*4, 0);
        cudaMemsetAsync(dn0, 0, (size_t)NP*4*4, 0);
        cudaMemsetAsync(dn2, 0, (size_t)NP*4*4, 0);
        cudaMemsetAsync(dn1, 0, (size_t)NA*4*4, 0);

        // queries per destination node type
        gemm128<<<GP, 256>>>(xp, q_w + (size_t)(l*2+0)*16384, q_b + (l*2+0)*128, qp, NP, 0, nullptr, nullptr);
        gemm128<<<GA, 256>>>(xa, q_w + (size_t)(l*2+1)*16384, q_b + (l*2+1)*128, qa, NA, 0, nullptr, nullptr);

        // e=0: writes (author -> paper)
        {
            int u = (l*3 + 0) * 2;
            gemm128<<<GA, 256>>>(xa, wc + (size_t)u*16384,     bc + u*128,     kr, NA, 0, nullptr, nullptr);
            gemm128<<<GA, 256>>>(xa, wc + (size_t)(u+1)*16384, bc + (u+1)*128, vr, NA, 0, nullptr, nullptr);
            edge_pass<<<GE, 256>>>(w_src, w_dst, kr, vr, qp, p_rel + (l*3+0)*4, dn0, m0, EE);
        }
        // e=1: rev_writes (paper -> author)
        {
            int u = (l*3 + 1) * 2;
            gemm128<<<GP, 256>>>(xp, wc + (size_t)u*16384,     bc + u*128,     kr, NP, 0, nullptr, nullptr);
            gemm128<<<GP, 256>>>(xp, wc + (size_t)(u+1)*16384, bc + (u+1)*128, vr, NP, 0, nullptr, nullptr);
            edge_pass<<<GE, 256>>>(r_src, r_dst, kr, vr, qa, p_rel + (l*3+1)*4, dn1, m1, EE);
        }
        // e=2: cites (paper -> paper)
        {
            int u = (l*3 + 2) * 2;
            gemm128<<<GP, 256>>>(xp, wc + (size_t)u*16384,     bc + u*128,     kr, NP, 0, nullptr, nullptr);
            gemm128<<<GP, 256>>>(xp, wc + (size_t)(u+1)*16384, bc + (u+1)*128, vr, NP, 0, nullptr, nullptr);
            edge_pass<<<GE, 256>>>(c_src, c_dst, kr, vr, qp, p_rel + (l*3+2)*4, dn2, m2, EE);
        }

        combine_paper <<<(NP*32 + 255)/256, 256>>>();
        combine_author<<<(NA*32 + 255)/256, 256>>>();

        // update with skip gate (in-place safe: Xold element read just before write)
        gemm128<<<GP, 256>>>(ap, a_w + (size_t)(l*2+0)*16384, a_b + (l*2+0)*128, xp, NP, 1, xp, skip + l*2 + 0);
        gemm128<<<GA, 256>>>(aa, a_w + (size_t)(l*2+1)*16384, a_b + (l*2+1)*128, xa, NA, 1, xa, skip + l*2 + 1);
    }

    // outputs: paper[:50000] then author[:25000], flattened
    cudaMemcpyAsync(out,                      xp, (size_t)50000*128*4, cudaMemcpyDeviceToDevice, 0);
    cudaMemcpyAsync(out + (size_t)50000*128,  xa, (size_t)25000*128*4, cudaMemcpyDeviceToDevice, 0);
}

// round 5
// speedup vs baseline: 1.6124x; 1.6124x over previous
#include <cuda_runtime.h>
#include <cuda_bf16.h>
#include <math.h>

#define NP 100000
#define NA 50000
#define EE 250000
#define HIDD 128
#define INV_SQRT_D 0.17677669529663687f
#define PADX 136
#define SMEM_GEMM ((2*128*PADX + 2*32*PADX) * (int)sizeof(__nv_bfloat16))

// ---------------- scratch (static device globals; no allocation) ----------------
__device__ float g_x_p[NP*HIDD];
__device__ float g_x_a[NA*HIDD];
__device__ float g_q_p[NP*HIDD];
__device__ float g_q_a[NA*HIDD];
__device__ float g_kr0[NA*HIDD];
__device__ float g_vr0[NA*HIDD];
__device__ float g_kr1[NP*HIDD];
__device__ float g_vr1[NP*HIDD];
__device__ float g_kr2[NP*HIDD];
__device__ float g_vr2[NP*HIDD];
__device__ float g_msg0[NP*HIDD];
__device__ float g_msg2[NP*HIDD];
__device__ float g_msg1[NA*HIDD];
__device__ float g_den0[NP*4];
__device__ float g_den2[NP*4];
__device__ float g_den1[NA*4];
__device__ float g_act_p[NP*HIDD];
__device__ float g_act_a[NA*HIDD];
__device__ float g_wc[12*HIDD*HIDD];       // combined (k_w@a_rel / v_w@m_rel)
__device__ float g_bc[12*HIDD];
__device__ __nv_bfloat16 g_wb[21*384*HIDD]; // stacked bf16 weights [u][384][128]

__device__ __forceinline__ float gelu_f(float x) {
    return 0.5f * x * (1.0f + erff(x * 0.70710678118654752f));
}

__device__ __forceinline__ unsigned s2u(const void* p) {
    return (unsigned)__cvta_generic_to_shared(p);
}

__device__ __forceinline__ void ldsm_x4(unsigned &r0, unsigned &r1, unsigned &r2, unsigned &r3, unsigned addr) {
    asm volatile("ldmatrix.sync.aligned.m8n8.x4.shared.b16 {%0,%1,%2,%3}, [%4];\n"
                 : "=r"(r0), "=r"(r1), "=r"(r2), "=r"(r3) : "r"(addr));
}
__device__ __forceinline__ void ldsm_x4t(unsigned &r0, unsigned &r1, unsigned &r2, unsigned &r3, unsigned addr) {
    asm volatile("ldmatrix.sync.aligned.m8n8.x4.trans.shared.b16 {%0,%1,%2,%3}, [%4];\n"
                 : "=r"(r0), "=r"(r1), "=r"(r2), "=r"(r3) : "r"(addr));
}
__device__ __forceinline__ void mma_bf16(float* d, const unsigned* a, const unsigned* b) {
    asm volatile("mma.sync.aligned.m16n8k16.row.col.f32.bf16.bf16.f32 "
                 "{%0,%1,%2,%3}, {%4,%5,%6,%7}, {%8,%9}, {%0,%1,%2,%3};\n"
                 : "+f"(d[0]), "+f"(d[1]), "+f"(d[2]), "+f"(d[3])
                 : "r"(a[0]), "r"(a[1]), "r"(a[2]), "r"(a[3]), "r"(b[0]), "r"(b[1]));
}

// ---------------- combined relation weights (fp32, tiny) ----------------
__global__ void make_wc(const float* __restrict__ kw, const float* __restrict__ kb,
                        const float* __restrict__ vw, const float* __restrict__ vb,
                        const float* __restrict__ arel, const float* __restrict__ mrel)
{
    int unit = blockIdx.x >> 3;
    int part = blockIdx.x & 7;
    int which = unit & 1;
    int le = unit >> 1;
    int e = le % 3;
    int l = le / 3;
    int s = (e == 0) ? 1 : 0;

    const float* W = (which ? vw : kw) + (size_t)(l*2 + s) * (HIDD*HIDD);
    const float* B = (which ? vb : kb) + (size_t)(l*2 + s) * HIDD;
    const float* R = (which ? mrel : arel) + (size_t)le * 4096;

    __shared__ float Rs[4096];
    for (int i = threadIdx.x; i < 4096; i += blockDim.x) Rs[i] = R[i];
    __syncthreads();

    float* outW = g_wc + (size_t)unit * (HIDD*HIDD);
    for (int idx = part*2048 + threadIdx.x; idx < (part+1)*2048; idx += blockDim.x) {
        int r = idx >> 7, col = idx & 127;
        int h = col >> 5, c = col & 31;
        float acc = 0.f;
        const float* wr = W + (size_t)r*HIDD + h*32;
        const float* rr = Rs + h*1024 + c;
        #pragma unroll
        for (int d = 0; d < 32; d++) acc = fmaf(wr[d], rr[d*32], acc);
        outW[idx] = acc;
    }
    if (part == 0) {
        for (int col = threadIdx.x; col < HIDD; col += blockDim.x) {
            int h = col >> 5, c = col & 31;
            float acc = 0.f;
            #pragma unroll
            for (int d = 0; d < 32; d++) acc = fmaf(B[h*32+d], Rs[h*1024 + d*32 + c], acc);
            g_bc[unit*HIDD + col] = acc;
        }
    }
}

// ---------------- stacked bf16 weight build: [Whi; Whi; Wlo] ----------------
// unit layout: 0=lin; 1+8l+{0..4} = paper group l {q_p, wc(e1,k), wc(e1,v), wc(e2,k), wc(e2,v)};
//              6+8l+{0..2} = author group l {q_a, wc(e0,k), wc(e0,v)}; 17+2l+t = a_w[l][t]
__global__ void wb_build(const float* __restrict__ lin_w, const float* __restrict__ q_w,
                         const float* __restrict__ a_w)
{
    int t = blockIdx.x * blockDim.x + threadIdx.x;
    if (t >= 21*16384) return;
    int u = t >> 14;
    int idx = t & 16383;
    const float* src;
    if (u == 0) src = lin_w;
    else if (u >= 17) src = a_w + (size_t)(u-17)*16384;
    else {
        int l = (u-1) / 8, r = (u-1) % 8;
        if (r == 0)       src = q_w + (size_t)(l*2)*16384;
        else if (r <= 4)  { int e = 1 + (r-1)/2, wv = (r-1)&1; src = g_wc + (size_t)((l*3+e)*2+wv)*16384; }
        else if (r == 5)  src = q_w + (size_t)(l*2+1)*16384;
        else              { int wv = r-6; src = g_wc + (size_t)((l*3)*2+wv)*16384; }
    }
    float w = src[idx];
    __nv_bfloat16 hi = __float2bfloat16(w);
    __nv_bfloat16 lo = __float2bfloat16(w - __bfloat162float(hi));
    int k = idx >> 7, n = idx & 127;
    __nv_bfloat16* dst = g_wb + (size_t)u*384*128;
    dst[(size_t)k*128 + n]       = hi;
    dst[(size_t)(128+k)*128 + n] = hi;
    dst[(size_t)(256+k)*128 + n] = lo;
}

// ---------------- tensor-core split-bf16 GEMM, multi-phase over nW weights ----------------
struct MO { float* Y[5]; const float* B[5]; };

__global__ __launch_bounds__(256, 2) void gemm_tc(
    const float* __restrict__ X, const __nv_bfloat16* __restrict__ Wb,
    MO mo, int N, int nW, int mode,
    const float* __restrict__ Xold, const float* __restrict__ skipPtr)
{
    extern __shared__ __align__(16) __nv_bfloat16 sm[];
    __nv_bfloat16* sXhi = sm;                 // [128][PADX]
    __nv_bfloat16* sXlo = sm + 128*PADX;      // [128][PADX]
    __nv_bfloat16* sWb  = sm + 2*128*PADX;    // [2][32][PADX]

    const int tid  = threadIdx.x;
    const int lane = tid & 31, warp = tid >> 5;
    const int wm = warp >> 2, wn = warp & 3;
    const int row0 = blockIdx.x * 128;

    // Load X tile, split fp32 -> bf16 hi/lo
    #pragma unroll
    for (int t = 0; t < 16; t++) {
        int li = tid + t*256;
        int r = li >> 5, c4 = (li & 31) << 2;
        float4 v = make_float4(0.f, 0.f, 0.f, 0.f);
        if (row0 + r < N) v = *(const float4*)&X[(size_t)(row0+r)*128 + c4];
        __nv_bfloat16 h0 = __float2bfloat16(v.x), h1 = __float2bfloat16(v.y),
                      h2 = __float2bfloat16(v.z), h3 = __float2bfloat16(v.w);
        __nv_bfloat16 l0 = __float2bfloat16(v.x - __bfloat162float(h0)),
                      l1 = __float2bfloat16(v.y - __bfloat162float(h1)),
                      l2 = __float2bfloat16(v.z - __bfloat162float(h2)),
                      l3 = __float2bfloat16(v.w - __bfloat162float(h3));
        uint2 ph, pl;
        ph.x = (unsigned)__bfloat16_as_ushort(h0) | ((unsigned)__bfloat16_as_ushort(h1) << 16);
        ph.y = (unsigned)__bfloat16_as_ushort(h2) | ((unsigned)__bfloat16_as_ushort(h3) << 16);
        pl.x = (unsigned)__bfloat16_as_ushort(l0) | ((unsigned)__bfloat16_as_ushort(l1) << 16);
        pl.y = (unsigned)__bfloat16_as_ushort(l2) | ((unsigned)__bfloat16_as_ushort(l3) << 16);
        *(uint2*)&sXhi[r*PADX + c4] = ph;
        *(uint2*)&sXlo[r*PADX + c4] = pl;
    }

    float gg = 1.f, og = 0.f;
    if (mode == 1) { float sv = *skipPtr; gg = 1.f/(1.f + expf(-sv)); og = 1.f - gg; }

    for (int p = 0; p < nW; p++) {
        const __nv_bfloat16* Wp = Wb + (size_t)p * 384 * 128;
        float acc[4][4][4];
        #pragma unroll
        for (int i = 0; i < 4; i++)
            #pragma unroll
            for (int j = 0; j < 4; j++)
                #pragma unroll
                for (int k = 0; k < 4; k++) acc[i][j][k] = 0.f;

        // prologue: stage 0 -> buf 0
        #pragma unroll
        for (int j = 0; j < 2; j++) {
            int li = tid + j*256;
            int r = li >> 4, c8 = (li & 15) << 3;
            *(uint4*)&sWb[r*PADX + c8] = *(const uint4*)&Wp[(size_t)r*128 + c8];
        }
        __syncthreads();

        for (int s = 0; s < 12; s++) {
            int bufc = s & 1;
            if (s < 11) {
                int bufn = bufc ^ 1;
                #pragma unroll
                for (int j = 0; j < 2; j++) {
                    int li = tid + j*256;
                    int r = li >> 4, c8 = (li & 15) << 3;
                    *(uint4*)&sWb[bufn*32*PADX + r*PADX + c8] =
                        *(const uint4*)&Wp[(size_t)((s+1)*32 + r)*128 + c8];
                }
            }
            const __nv_bfloat16* Xsrc = ((s >> 2) == 1) ? sXlo : sXhi;
            int kbase = (s & 3) * 32;
            #pragma unroll
            for (int ks = 0; ks < 2; ks++) {
                int kk = kbase + ks*16;
                unsigned a[4][4];
                #pragma unroll
                for (int mt = 0; mt < 4; mt++) {
                    unsigned ad = s2u(&Xsrc[(wm*64 + mt*16 + (lane & 15))*PADX + kk + (lane >> 4)*8]);
                    ldsm_x4(a[mt][0], a[mt][1], a[mt][2], a[mt][3], ad);
                }
                unsigned b[4][2];
                #pragma unroll
                for (int ntp = 0; ntp < 2; ntp++) {
                    int m = lane >> 3;
                    unsigned ad = s2u(&sWb[bufc*32*PADX + (ks*16 + (m & 1)*8 + (lane & 7))*PADX
                                           + wn*32 + ntp*16 + (m >> 1)*8]);
                    unsigned r0, r1, r2, r3;
                    ldsm_x4t(r0, r1, r2, r3, ad);
                    b[ntp*2][0] = r0; b[ntp*2][1] = r1;
                    b[ntp*2+1][0] = r2; b[ntp*2+1][1] = r3;
                }
                #pragma unroll
                for (int mt = 0; mt < 4; mt++)
                    #pragma unroll
                    for (int nt = 0; nt < 4; nt++)
                        mma_bf16(acc[mt][nt], a[mt], b[nt]);
            }
            __syncthreads();
        }

        // epilogue
        float* Yp = mo.Y[p];
        const float* Bp = mo.B[p];
        #pragma unroll
        for (int mt = 0; mt < 4; mt++) {
            int r = row0 + wm*64 + mt*16 + (lane >> 2);
            #pragma unroll
            for (int nt = 0; nt < 4; nt++) {
                int c = wn*32 + nt*8 + ((lane & 3) << 1);
                float b0 = Bp[c], b1 = Bp[c+1];
                if (r < N) {
                    float2 o = make_float2(acc[mt][nt][0] + b0, acc[mt][nt][1] + b1);
                    if (mode == 1) {
                        float2 xo = *(const float2*)&Xold[(size_t)r*128 + c];
                        o.x = gg*o.x + og*xo.x; o.y = gg*o.y + og*xo.y;
                    }
                    *(float2*)&Yp[(size_t)r*128 + c] = o;
                }
                int r2 = r + 8;
                if (r2 < N) {
                    float2 o = make_float2(acc[mt][nt][2] + b0, acc[mt][nt][3] + b1);
                    if (mode == 1) {
                        float2 xo = *(const float2*)&Xold[(size_t)r2*128 + c];
                        o.x = gg*o.x + og*xo.x; o.y = gg*o.y + og*xo.y;
                    }
                    *(float2*)&Yp[(size_t)r2*128 + c] = o;
                }
            }
        }
    }
}

// ---------------- author embedding gather ----------------
__global__ void gather_embed(const float* __restrict__ tab, const int* __restrict__ idx)
{
    int t = blockIdx.x * blockDim.x + threadIdx.x;
    if (t >= NA*32) return;
    int row = t >> 5, c = t & 31;
    ((float4*)g_x_a)[t] = ((const float4*)tab)[(size_t)idx[row]*32 + c];
}

// ---------------- fused edge pass ----------------
__global__ void edge_pass(const int* __restrict__ src, const int* __restrict__ dst,
                          const float* __restrict__ KR, const float* __restrict__ VR,
                          const float* __restrict__ Q, const float* __restrict__ prel,
                          float* __restrict__ den, float* __restrict__ msg, int E)
{
    int w = (blockIdx.x * blockDim.x + threadIdx.x) >> 5;
    int lane = threadIdx.x & 31;
    if (w >= E) return;
    int s = src[w];
    int d = dst[w];
    const float4 kr = *(const float4*)&KR[(size_t)s*128 + lane*4];
    const float4 q4 = *(const float4*)&Q [(size_t)d*128 + lane*4];
    const float4 vr = *(const float4*)&VR[(size_t)s*128 + lane*4];
    float p = kr.x*q4.x + kr.y*q4.y + kr.z*q4.z + kr.w*q4.w;
    p += __shfl_xor_sync(0xffffffffu, p, 4);
    p += __shfl_xor_sync(0xffffffffu, p, 2);
    p += __shfl_xor_sync(0xffffffffu, p, 1);
    int h = lane >> 3;
    float ex = expf(p * prel[h] * INV_SQRT_D);
    if ((lane & 7) == 0) atomicAdd(&den[(size_t)d*4 + h], ex);
    float* ptr = &msg[(size_t)d*128 + lane*4];
    asm volatile("red.global.add.v4.f32 [%0], {%1, %2, %3, %4};"
                 :: "l"(ptr), "f"(vr.x*ex), "f"(vr.y*ex), "f"(vr.z*ex), "f"(vr.w*ex)
                 : "memory");
}

// ---------------- combine ----------------
__global__ void combine_paper()
{
    int t = blockIdx.x * blockDim.x + threadIdx.x;
    if (t >= NP*32) return;
    int row = t >> 5, h = (t & 31) >> 3;
    float d0 = g_den0[row*4 + h] + 1e-16f;
    float d2 = g_den2[row*4 + h] + 1e-16f;
    float4 a = ((const float4*)g_msg0)[t];
    float4 b = ((const float4*)g_msg2)[t];
    float4 o;
    o.x = gelu_f(0.5f*(a.x/d0 + b.x/d2));
    o.y = gelu_f(0.5f*(a.y/d0 + b.y/d2));
    o.z = gelu_f(0.5f*(a.z/d0 + b.z/d2));
    o.w = gelu_f(0.5f*(a.w/d0 + b.w/d2));
    ((float4*)g_act_p)[t] = o;
}

__global__ void combine_author()
{
    int t = blockIdx.x * blockDim.x + threadIdx.x;
    if (t >= NA*32) return;
    int row = t >> 5, h = (t & 31) >> 3;
    float d1 = g_den1[row*4 + h] + 1e-16f;
    float4 a = ((const float4*)g_msg1)[t];
    float4 o;
    o.x = gelu_f(a.x/d1);
    o.y = gelu_f(a.y/d1);
    o.z = gelu_f(a.z/d1);
    o.w = gelu_f(a.w/d1);
    ((float4*)g_act_a)[t] = o;
}

// ---------------- driver ----------------
extern "C" void kernel_launch(void* const* d_in, const int* in_sizes, int n_in,
                              void* d_out, int out_size)
{
    const float* x_paper    = (const float*)d_in[0];
    const int*   author_idx = (const int*)  d_in[1];
    const float* embed      = (const float*)d_in[2];
    const float* lin_w      = (const float*)d_in[3];
    const float* lin_b      = (const float*)d_in[4];
    const float* k_w        = (const float*)d_in[5];
    const float* k_b        = (const float*)d_in[6];
    const float* q_w        = (const float*)d_in[7];
    const float* q_b        = (const float*)d_in[8];
    const float* v_w        = (const float*)d_in[9];
    const float* v_b        = (const float*)d_in[10];
    const float* a_rel      = (const float*)d_in[11];
    const float* m_rel      = (const float*)d_in[12];
    const float* p_rel      = (const float*)d_in[13];
    const float* skip       = (const float*)d_in[14];
    const float* a_w        = (const float*)d_in[15];
    const float* a_b        = (const float*)d_in[16];
    const int*   w_src      = (const int*)  d_in[17];
    const int*   w_dst      = (const int*)  d_in[18];
    const int*   r_src      = (const int*)  d_in[19];
    const int*   r_dst      = (const int*)  d_in[20];
    const int*   c_src      = (const int*)  d_in[21];
    const int*   c_dst      = (const int*)  d_in[22];
    float* out = (float*)d_out;

    float *xp, *xa, *qp, *qa, *kr0, *vr0, *kr1, *vr1, *kr2, *vr2;
    float *m0, *m2, *m1, *dn0, *dn2, *dn1, *ap, *aa, *bc;
    __nv_bfloat16 *wb;
    cudaGetSymbolAddress((void**)&xp,  g_x_p);
    cudaGetSymbolAddress((void**)&xa,  g_x_a);
    cudaGetSymbolAddress((void**)&qp,  g_q_p);
    cudaGetSymbolAddress((void**)&qa,  g_q_a);
    cudaGetSymbolAddress((void**)&kr0, g_kr0);
    cudaGetSymbolAddress((void**)&vr0, g_vr0);
    cudaGetSymbolAddress((void**)&kr1, g_kr1);
    cudaGetSymbolAddress((void**)&vr1, g_vr1);
    cudaGetSymbolAddress((void**)&kr2, g_kr2);
    cudaGetSymbolAddress((void**)&vr2, g_vr2);
    cudaGetSymbolAddress((void**)&m0,  g_msg0);
    cudaGetSymbolAddress((void**)&m2,  g_msg2);
    cudaGetSymbolAddress((void**)&m1,  g_msg1);
    cudaGetSymbolAddress((void**)&dn0, g_den0);
    cudaGetSymbolAddress((void**)&dn2, g_den2);
    cudaGetSymbolAddress((void**)&dn1, g_den1);
    cudaGetSymbolAddress((void**)&ap,  g_act_p);
    cudaGetSymbolAddress((void**)&aa,  g_act_a);
    cudaGetSymbolAddress((void**)&bc,  g_bc);
    cudaGetSymbolAddress((void**)&wb,  g_wb);

    cudaFuncSetAttribute(gemm_tc, cudaFuncAttributeMaxDynamicSharedMemorySize, SMEM_GEMM);

    const int GP = (NP + 127) / 128;
    const int GA = (NA + 127) / 128;
    const int GE = (EE * 32 + 255) / 256;

    make_wc<<<96, 256>>>(k_w, k_b, v_w, v_b, a_rel, m_rel);
    wb_build<<<(21*16384 + 255)/256, 256>>>(lin_w, q_w, a_w);

    // input projections
    {
        MO mo = {};
        mo.Y[0] = xp; mo.B[0] = lin_b;
        gemm_tc<<<GP, 256, SMEM_GEMM>>>(x_paper, wb, mo, NP, 1, 0, nullptr, nullptr);
    }
    gather_embed<<<(NA*32 + 255)/256, 256>>>(embed, author_idx);

    for (int l = 0; l < 2; l++) {
        cudaMemsetAsync(m0,  0, (size_t)NP*128*4, 0);
        cudaMemsetAsync(m2,  0, (size_t)NP*128*4, 0);
        cudaMemsetAsync(m1,  0, (size_t)NA*128*4, 0);
        cudaMemsetAsync(dn0, 0, (size_t)NP*4*4, 0);
        cudaMemsetAsync(dn2, 0, (size_t)NP*4*4, 0);
        cudaMemsetAsync(dn1, 0, (size_t)NA*4*4, 0);

        // paper group: q_p, kr(e1), vr(e1), kr(e2), vr(e2) — one X pass
        {
            MO mo = {};
            mo.Y[0] = qp;  mo.B[0] = q_b + (size_t)(l*2)*128;
            mo.Y[1] = kr1; mo.B[1] = bc + ((l*3+1)*2+0)*128;
            mo.Y[2] = vr1; mo.B[2] = bc + ((l*3+1)*2+1)*128;
            mo.Y[3] = kr2; mo.B[3] = bc + ((l*3+2)*2+0)*128;
            mo.Y[4] = vr2; mo.B[4] = bc + ((l*3+2)*2+1)*128;
            gemm_tc<<<GP, 256, SMEM_GEMM>>>(xp, wb + (size_t)(1 + 8*l)*384*128, mo, NP, 5, 0, nullptr, nullptr);
        }
        // author group: q_a, kr(e0), vr(e0)
        {
            MO mo = {};
            mo.Y[0] = qa;  mo.B[0] = q_b + (size_t)(l*2+1)*128;
            mo.Y[1] = kr0; mo.B[1] = bc + ((l*3+0)*2+0)*128;
            mo.Y[2] = vr0; mo.B[2] = bc + ((l*3+0)*2+1)*128;
            gemm_tc<<<GA, 256, SMEM_GEMM>>>(xa, wb + (size_t)(6 + 8*l)*384*128, mo, NA, 3, 0, nullptr, nullptr);
        }

        edge_pass<<<GE, 256>>>(w_src, w_dst, kr0, vr0, qp, p_rel + (l*3+0)*4, dn0, m0, EE);
        edge_pass<<<GE, 256>>>(r_src, r_dst, kr1, vr1, qa, p_rel + (l*3+1)*4, dn1, m1, EE);
        edge_pass<<<GE, 256>>>(c_src, c_dst, kr2, vr2, qp, p_rel + (l*3+2)*4, dn2, m2, EE);

        combine_paper <<<(NP*32 + 255)/256, 256>>>();
        combine_author<<<(NA*32 + 255)/256, 256>>>();

        // updates with skip gate
        {
            MO mo = {};
            mo.Y[0] = xp; mo.B[0] = a_b + (size_t)(l*2)*128;
            gemm_tc<<<GP, 256, SMEM_GEMM>>>(ap, wb + (size_t)(17 + 2*l)*384*128, mo, NP, 1, 1, xp, skip + l*2 + 0);
        }
        {
            MO mo = {};
            mo.Y[0] = xa; mo.B[0] = a_b + (size_t)(l*2+1)*128;
            gemm_tc<<<GA, 256, SMEM_GEMM>>>(aa, wb + (size_t)(18 + 2*l)*384*128, mo, NA, 1, 1, xa, skip + l*2 + 1);
        }
    }

    cudaMemcpyAsync(out,                     xp, (size_t)50000*128*4, cudaMemcpyDeviceToDevice, 0);
    cudaMemcpyAsync(out + (size_t)50000*128, xa, (size_t)25000*128*4, cudaMemcpyDeviceToDevice, 0);
}